// round 3
// baseline (speedup 1.0000x reference)
#include <cuda_runtime.h>
#include <cstdint>

// Problem constants (fixed by the reference setup_inputs)
#define TOKENS   4096
#define IN_F     8192
#define OUT_F    8192
#define NGROUPS  (IN_F / 64)      // 128 scale groups per output row
#define OCHUNKS  64               // split of the o-reduction for parallelism
#define O_PER_CHUNK (OUT_F / OCHUNKS)  // 128

// Scratch (allocation-free rule: __device__ globals)
__device__ float g_partial[OCHUNKS * IN_F];   // 2 MB partial v sums
__device__ float g_v[IN_F];                   // final v vector

__constant__ float c_nf4[16] = {
    -1.0f, -0.6961928009986877f, -0.5250730514526367f, -0.39491748809814453f,
    -0.28444138169288635f, -0.18477343022823334f, -0.09105003625154495f, 0.0f,
    0.07958029955625534f, 0.16093020141124725f, 0.24611230194568634f,
    0.33791524171829224f, 0.44070982933044434f, 0.5626170039176941f,
    0.7229568362236023f, 1.0f
};

// ---------------------------------------------------------------------------
// Kernel 1: v_partial[oc][i] = sum_{o in chunk oc} NF4[codes[o,i]] * scales[o, i/64] * w2[o]
// Each thread owns 4 consecutive columns i (one int4 of codes per o).
// Grid: (IN_F / (4*256), OCHUNKS), block 256.
// ---------------------------------------------------------------------------
__global__ void __launch_bounds__(256) k_dequant_reduce(
    const int*   __restrict__ codes,   // [OUT_F, IN_F]
    const float* __restrict__ scales,  // [OUT_F, NGROUPS]
    const float* __restrict__ w2)      // [OUT_F]
{
    // Bank-conflict-free NF4 table: tbl[c*32 + lane] == NF4[c].
    __shared__ float tbl[16 * 32];
    for (int idx = threadIdx.x; idx < 16 * 32; idx += blockDim.x)
        tbl[idx] = c_nf4[idx >> 5];
    __syncthreads();

    const int lane = threadIdx.x & 31;
    const float* lt = &tbl[lane];                 // lt[c<<5] hits lane's own bank

    const int i  = (blockIdx.x * blockDim.x + threadIdx.x) * 4;  // column base
    const int oc = blockIdx.y;
    const int o0 = oc * O_PER_CHUNK;
    const int grp = i >> 6;                       // same scale group for i..i+3

    const int4* cptr = reinterpret_cast<const int4*>(codes) +
                       (((size_t)o0 * IN_F + i) >> 2);
    const size_t cstride = IN_F / 4;              // int4 stride per o

    float s0 = 0.f, s1 = 0.f, s2 = 0.f, s3 = 0.f;

#pragma unroll 8
    for (int o = o0; o < o0 + O_PER_CHUNK; ++o) {
        int4 c = __ldg(cptr);
        cptr += cstride;
        float s = __ldg(&w2[o]) * __ldg(&scales[(size_t)o * NGROUPS + grp]);
        s0 += s * lt[c.x << 5];
        s1 += s * lt[c.y << 5];
        s2 += s * lt[c.z << 5];
        s3 += s * lt[c.w << 5];
    }

    float4 r = make_float4(s0, s1, s2, s3);
    *reinterpret_cast<float4*>(&g_partial[(size_t)oc * IN_F + i]) = r;
}

// ---------------------------------------------------------------------------
// Kernel 1b: v[i] = sum_oc partial[oc][i]   (fixed-order, deterministic)
// ---------------------------------------------------------------------------
__global__ void __launch_bounds__(256) k_reduce_chunks()
{
    const int i = blockIdx.x * blockDim.x + threadIdx.x;
    float s = 0.f;
#pragma unroll
    for (int c = 0; c < OCHUNKS; ++c)
        s += g_partial[(size_t)c * IN_F + i];
    g_v[i] = s;
}

// ---------------------------------------------------------------------------
// Kernel 2: out[t] = dot(x[t, :], v)   — one block per token.
// ---------------------------------------------------------------------------
__global__ void __launch_bounds__(256) k_xv(
    const float* __restrict__ x,      // [TOKENS, IN_F]
    float*       __restrict__ out)    // [TOKENS]
{
    const int t = blockIdx.x;
    const float4* xr = reinterpret_cast<const float4*>(x + (size_t)t * IN_F);
    const float4* vr = reinterpret_cast<const float4*>(g_v);

    float sum = 0.f;
#pragma unroll
    for (int k = 0; k < (IN_F / 4) / 256; ++k) {
        int j = threadIdx.x + k * 256;
        float4 a = __ldg(&xr[j]);
        float4 b = vr[j];
        sum += a.x * b.x + a.y * b.y + a.z * b.z + a.w * b.w;
    }

    // Block reduction: warp shuffle then cross-warp via shared.
    for (int off = 16; off > 0; off >>= 1)
        sum += __shfl_down_sync(0xFFFFFFFFu, sum, off);

    __shared__ float warp_sums[8];
    const int wid = threadIdx.x >> 5;
    const int lane = threadIdx.x & 31;
    if (lane == 0) warp_sums[wid] = sum;
    __syncthreads();

    if (wid == 0) {
        float v = (lane < 8) ? warp_sums[lane] : 0.f;
        for (int off = 4; off > 0; off >>= 1)
            v += __shfl_down_sync(0xFFFFFFFFu, v, off);
        if (lane == 0) out[t] = v;
    }
}

// ---------------------------------------------------------------------------
// Launch
// ---------------------------------------------------------------------------
extern "C" void kernel_launch(void* const* d_in, const int* in_sizes, int n_in,
                              void* d_out, int out_size)
{
    const float* x      = (const float*)d_in[0];   // [4096, 8192] f32
    const int*   codes  = (const int*)  d_in[1];   // [8192, 8192] i32 (0..15)
    const float* scales = (const float*)d_in[2];   // [8192, 128]  f32
    const float* w2     = (const float*)d_in[3];   // [1, 8192]    f32
    float*       out    = (float*)d_out;           // [4096, 1]    f32

    (void)in_sizes; (void)n_in; (void)out_size;

    dim3 g1(IN_F / (4 * 256), OCHUNKS);            // (8, 64)
    k_dequant_reduce<<<g1, 256>>>(codes, scales, w2);
    k_reduce_chunks<<<IN_F / 256, 256>>>();        // 32 blocks
    k_xv<<<TOKENS, 256>>>(x, out);
}

// round 4
// speedup vs baseline: 1.1085x; 1.1085x over previous
#include <cuda_runtime.h>
#include <cstdint>

// Problem constants (fixed by the reference setup_inputs)
#define TOKENS   4096
#define IN_F     8192
#define OUT_F    8192
#define NGROUPS  (IN_F / 64)      // 128 scale groups per output row
#define OCHUNKS  128              // split of the o-reduction for parallelism
#define O_PER_CHUNK (OUT_F / OCHUNKS)  // 64

// Scratch (allocation-free rule: __device__ globals)
__device__ float g_partial[OCHUNKS * IN_F];   // 4 MB partial v sums
__device__ float g_v[IN_F];                   // final v vector

__constant__ float c_nf4[16] = {
    -1.0f, -0.6961928009986877f, -0.5250730514526367f, -0.39491748809814453f,
    -0.28444138169288635f, -0.18477343022823334f, -0.09105003625154495f, 0.0f,
    0.07958029955625534f, 0.16093020141124725f, 0.24611230194568634f,
    0.33791524171829224f, 0.44070982933044434f, 0.5626170039176941f,
    0.7229568362236023f, 1.0f
};

// ---------------------------------------------------------------------------
// Kernel 1: v_partial[oc][i] = sum_{o in chunk oc} NF4[codes[o,i]] * scales[o, i/64] * w2[o]
// Each thread owns 4 consecutive columns i (one int4 of codes per o).
// Grid: (IN_F / (4*256), OCHUNKS) = (8, 128), block 256.
// ---------------------------------------------------------------------------
__global__ void __launch_bounds__(256) k_dequant_reduce(
    const int*   __restrict__ codes,   // [OUT_F, IN_F]
    const float* __restrict__ scales,  // [OUT_F, NGROUPS]
    const float* __restrict__ w2)      // [OUT_F]
{
    // Bank-conflict-free NF4 table: tbl[c*32 + lane] == NF4[c].
    __shared__ float tbl[16 * 32];
    for (int idx = threadIdx.x; idx < 16 * 32; idx += blockDim.x)
        tbl[idx] = c_nf4[idx >> 5];
    __syncthreads();

    const int lane = threadIdx.x & 31;
    const float* lt = &tbl[lane];                 // lt[c<<5] hits lane's own bank

    const int i  = (blockIdx.x * blockDim.x + threadIdx.x) * 4;  // column base
    const int oc = blockIdx.y;
    const int o0 = oc * O_PER_CHUNK;
    const int grp = i >> 6;                       // same scale group for i..i+3

    const int4* cptr = reinterpret_cast<const int4*>(codes) +
                       (((size_t)o0 * IN_F + i) >> 2);
    const size_t cstride = IN_F / 4;              // int4 stride per o

    float s0 = 0.f, s1 = 0.f, s2 = 0.f, s3 = 0.f;

#pragma unroll 8
    for (int o = o0; o < o0 + O_PER_CHUNK; ++o) {
        int4 c = __ldcs(cptr);                    // streaming: no reuse, evict-first
        cptr += cstride;
        float s = __ldg(&w2[o]) * __ldg(&scales[(size_t)o * NGROUPS + grp]);
        s0 += s * lt[c.x << 5];
        s1 += s * lt[c.y << 5];
        s2 += s * lt[c.z << 5];
        s3 += s * lt[c.w << 5];
    }

    float4 r = make_float4(s0, s1, s2, s3);
    *reinterpret_cast<float4*>(&g_partial[(size_t)oc * IN_F + i]) = r;
}

// ---------------------------------------------------------------------------
// Kernel 1b: v[i] = sum_oc partial[oc][i]   (fixed-order, deterministic)
// ---------------------------------------------------------------------------
__global__ void __launch_bounds__(256) k_reduce_chunks()
{
    const int i = blockIdx.x * blockDim.x + threadIdx.x;
    float s = 0.f;
#pragma unroll
    for (int c = 0; c < OCHUNKS; ++c)
        s += g_partial[(size_t)c * IN_F + i];
    g_v[i] = s;
}

// ---------------------------------------------------------------------------
// Kernel 2: out[t] = dot(x[t, :], v)   — one block per token.
// ---------------------------------------------------------------------------
__global__ void __launch_bounds__(256) k_xv(
    const float* __restrict__ x,      // [TOKENS, IN_F]
    float*       __restrict__ out)    // [TOKENS]
{
    const int t = blockIdx.x;
    const float4* xr = reinterpret_cast<const float4*>(x + (size_t)t * IN_F);
    const float4* vr = reinterpret_cast<const float4*>(g_v);

    float sum = 0.f;
#pragma unroll
    for (int k = 0; k < (IN_F / 4) / 256; ++k) {
        int j = threadIdx.x + k * 256;
        float4 a = __ldcs(&xr[j]);                // streaming: x read exactly once
        float4 b = __ldg(&vr[j]);                 // g_v is hot in L2
        sum += a.x * b.x + a.y * b.y + a.z * b.z + a.w * b.w;
    }

    // Block reduction: warp shuffle then cross-warp via shared.
    for (int off = 16; off > 0; off >>= 1)
        sum += __shfl_down_sync(0xFFFFFFFFu, sum, off);

    __shared__ float warp_sums[8];
    const int wid = threadIdx.x >> 5;
    const int lane = threadIdx.x & 31;
    if (lane == 0) warp_sums[wid] = sum;
    __syncthreads();

    if (wid == 0) {
        float v = (lane < 8) ? warp_sums[lane] : 0.f;
        for (int off = 4; off > 0; off >>= 1)
            v += __shfl_down_sync(0xFFFFFFFFu, v, off);
        if (lane == 0) out[t] = v;
    }
}

// ---------------------------------------------------------------------------
// Launch
// ---------------------------------------------------------------------------
extern "C" void kernel_launch(void* const* d_in, const int* in_sizes, int n_in,
                              void* d_out, int out_size)
{
    const float* x      = (const float*)d_in[0];   // [4096, 8192] f32
    const int*   codes  = (const int*)  d_in[1];   // [8192, 8192] i32 (0..15)
    const float* scales = (const float*)d_in[2];   // [8192, 128]  f32
    const float* w2     = (const float*)d_in[3];   // [1, 8192]    f32
    float*       out    = (float*)d_out;           // [4096, 1]    f32

    (void)in_sizes; (void)n_in; (void)out_size;

    dim3 g1(IN_F / (4 * 256), OCHUNKS);            // (8, 128)
    k_dequant_reduce<<<g1, 256>>>(codes, scales, w2);
    k_reduce_chunks<<<IN_F / 256, 256>>>();        // 32 blocks
    k_xv<<<TOKENS, 256>>>(x, out);
}

// round 5
// speedup vs baseline: 1.1116x; 1.0027x over previous
#include <cuda_runtime.h>
#include <cstdint>

// Problem constants (fixed by the reference setup_inputs)
#define TOKENS   4096
#define IN_F     8192
#define OUT_F    8192
#define NGROUPS  (IN_F / 64)      // 128 scale groups per output row
#define OCHUNKS  128              // split of the o-reduction for parallelism
#define O_PER_CHUNK (OUT_F / OCHUNKS)  // 64

// Scratch (allocation-free rule: __device__ globals)
__device__ float g_partial[OCHUNKS * IN_F];   // 4 MB partial v sums
__device__ float g_v[IN_F];                   // final v vector

__constant__ float c_nf4[16] = {
    -1.0f, -0.6961928009986877f, -0.5250730514526367f, -0.39491748809814453f,
    -0.28444138169288635f, -0.18477343022823334f, -0.09105003625154495f, 0.0f,
    0.07958029955625534f, 0.16093020141124725f, 0.24611230194568634f,
    0.33791524171829224f, 0.44070982933044434f, 0.5626170039176941f,
    0.7229568362236023f, 1.0f
};

// ---------------------------------------------------------------------------
// Kernel 1: v_partial[oc][i] = sum_{o in chunk oc} NF4[codes[o,i]] * scales[o, i/64] * w2[o]
// Each thread owns 4 consecutive columns i (one int4 of codes per o).
// Grid: (IN_F / (4*256), OCHUNKS) = (8, 128), block 256.
// ---------------------------------------------------------------------------
__global__ void __launch_bounds__(256) k_dequant_reduce(
    const int*   __restrict__ codes,   // [OUT_F, IN_F]
    const float* __restrict__ scales,  // [OUT_F, NGROUPS]
    const float* __restrict__ w2)      // [OUT_F]
{
    // Bank-conflict-free NF4 table: tbl[c*32 + lane] == NF4[c].
    __shared__ float tbl[16 * 32];
    for (int idx = threadIdx.x; idx < 16 * 32; idx += blockDim.x)
        tbl[idx] = c_nf4[idx >> 5];
    __syncthreads();

    const int lane = threadIdx.x & 31;
    const float* lt = &tbl[lane];                 // lt[c<<5] hits lane's own bank

    const int i  = (blockIdx.x * blockDim.x + threadIdx.x) * 4;  // column base
    const int oc = blockIdx.y;
    const int o0 = oc * O_PER_CHUNK;
    const int grp = i >> 6;                       // same scale group for i..i+3

    const int4* cptr = reinterpret_cast<const int4*>(codes) +
                       (((size_t)o0 * IN_F + i) >> 2);
    const size_t cstride = IN_F / 4;              // int4 stride per o

    float s0 = 0.f, s1 = 0.f, s2 = 0.f, s3 = 0.f;

#pragma unroll 8
    for (int o = o0; o < o0 + O_PER_CHUNK; ++o) {
        int4 c = __ldcs(cptr);                    // streaming: no reuse, evict-first
        cptr += cstride;
        float s = __ldg(&w2[o]) * __ldg(&scales[(size_t)o * NGROUPS + grp]);
        s0 += s * lt[c.x << 5];
        s1 += s * lt[c.y << 5];
        s2 += s * lt[c.z << 5];
        s3 += s * lt[c.w << 5];
    }

    float4 r = make_float4(s0, s1, s2, s3);
    *reinterpret_cast<float4*>(&g_partial[(size_t)oc * IN_F + i]) = r;
}

// ---------------------------------------------------------------------------
// Kernel 1b: v[i] = sum_oc partial[oc][i]   (fixed-order, deterministic)
// ---------------------------------------------------------------------------
__global__ void __launch_bounds__(256) k_reduce_chunks()
{
    const int i = blockIdx.x * blockDim.x + threadIdx.x;
    float s = 0.f;
#pragma unroll
    for (int c = 0; c < OCHUNKS; ++c)
        s += g_partial[(size_t)c * IN_F + i];
    g_v[i] = s;
}

// ---------------------------------------------------------------------------
// Kernel 2: out[t] = dot(x[t, :], v)   — one block per token.
// ---------------------------------------------------------------------------
__global__ void __launch_bounds__(256) k_xv(
    const float* __restrict__ x,      // [TOKENS, IN_F]
    float*       __restrict__ out)    // [TOKENS]
{
    const int t = blockIdx.x;
    const float4* xr = reinterpret_cast<const float4*>(x + (size_t)t * IN_F);
    const float4* vr = reinterpret_cast<const float4*>(g_v);

    float sum = 0.f;
#pragma unroll
    for (int k = 0; k < (IN_F / 4) / 256; ++k) {
        int j = threadIdx.x + k * 256;
        float4 a = __ldcs(&xr[j]);                // streaming: x read exactly once
        float4 b = __ldg(&vr[j]);                 // g_v is hot in L2
        sum += a.x * b.x + a.y * b.y + a.z * b.z + a.w * b.w;
    }

    // Block reduction: warp shuffle then cross-warp via shared.
    for (int off = 16; off > 0; off >>= 1)
        sum += __shfl_down_sync(0xFFFFFFFFu, sum, off);

    __shared__ float warp_sums[8];
    const int wid = threadIdx.x >> 5;
    const int lane = threadIdx.x & 31;
    if (lane == 0) warp_sums[wid] = sum;
    __syncthreads();

    if (wid == 0) {
        float v = (lane < 8) ? warp_sums[lane] : 0.f;
        for (int off = 4; off > 0; off >>= 1)
            v += __shfl_down_sync(0xFFFFFFFFu, v, off);
        if (lane == 0) out[t] = v;
    }
}

// ---------------------------------------------------------------------------
// Launch
// ---------------------------------------------------------------------------
extern "C" void kernel_launch(void* const* d_in, const int* in_sizes, int n_in,
                              void* d_out, int out_size)
{
    const float* x      = (const float*)d_in[0];   // [4096, 8192] f32
    const int*   codes  = (const int*)  d_in[1];   // [8192, 8192] i32 (0..15)
    const float* scales = (const float*)d_in[2];   // [8192, 128]  f32
    const float* w2     = (const float*)d_in[3];   // [1, 8192]    f32
    float*       out    = (float*)d_out;           // [4096, 1]    f32

    (void)in_sizes; (void)n_in; (void)out_size;

    dim3 g1(IN_F / (4 * 256), OCHUNKS);            // (8, 128)
    k_dequant_reduce<<<g1, 256>>>(codes, scales, w2);
    k_reduce_chunks<<<IN_F / 256, 256>>>();        // 32 blocks
    k_xv<<<TOKENS, 256>>>(x, out);
}